// round 7
// baseline (speedup 1.0000x reference)
#include <cuda_runtime.h>
#include <cuda_bf16.h>
#include <cstdint>

static constexpr int B_ = 32, S_ = 128, E_ = 512, F_ = 2048;
static constexpr int KC = 32;   // K per chunk

// per-buffer SMEM: A_hi 8K | A_lo 8K | B_hi 4K | B_lo 4K (128B rows, half used)
static constexpr int OFF_A_HI = 0;
static constexpr int OFF_A_LO = 8192;
static constexpr int OFF_B_HI = 16384;
static constexpr int OFF_B_LO = 20480;
static constexpr int BUF_SZ   = 24576;
static constexpr int SM_DYN   = 2 * BUF_SZ + 1024;   // 50176

// ---- scratch ----
__device__ uint32_t g_H[(size_t)S_ * B_ * F_];      // packed (hi | lo<<16) [s][b][f]
__device__ float    g_P[2][(size_t)B_ * S_ * E_];   // gemm2 k-split partials [b][s][e]

// ============ helpers ============
__device__ __forceinline__ uint32_t s2u(const void* p) {
    uint32_t a;
    asm("{ .reg .u64 t; cvta.to.shared.u64 t, %1; cvt.u32.u64 %0, t; }" : "=r"(a) : "l"(p));
    return a;
}
__device__ __forceinline__ uint32_t packbf(float lo, float hi) {   // lo -> low 16 bits
    uint32_t r; asm("cvt.rn.bf16x2.f32 %0, %1, %2;" : "=r"(r) : "f"(hi), "f"(lo)); return r;
}
__device__ __forceinline__ float bflo(uint32_t p) { return __uint_as_float(p << 16); }
__device__ __forceinline__ float bfhi(uint32_t p) { return __uint_as_float(p & 0xFFFF0000u); }
__device__ __forceinline__ void sts32(uint32_t a, uint32_t v) {
    asm volatile("st.shared.b32 [%0], %1;" :: "r"(a), "r"(v) : "memory");
}
__device__ __forceinline__ void sts64(uint32_t a, uint32_t v0, uint32_t v1) {
    asm volatile("st.shared.v2.b32 [%0], {%1, %2};" :: "r"(a), "r"(v0), "r"(v1) : "memory");
}
__device__ __forceinline__ void ldmA(uint32_t* r, uint32_t addr) {  // x4 trans: [k][m]
    asm volatile("ldmatrix.sync.aligned.m8n8.x4.trans.shared.b16 {%0,%1,%2,%3}, [%4];"
                 : "=r"(r[0]), "=r"(r[1]), "=r"(r[2]), "=r"(r[3]) : "r"(addr));
}
__device__ __forceinline__ void ldmB(uint32_t* r, uint32_t addr) {  // x4: [n][k]
    asm volatile("ldmatrix.sync.aligned.m8n8.x4.shared.b16 {%0,%1,%2,%3}, [%4];"
                 : "=r"(r[0]), "=r"(r[1]), "=r"(r[2]), "=r"(r[3]) : "r"(addr));
}
__device__ __forceinline__ void mma16816(float* c, const uint32_t* a, const uint32_t* b) {
    asm volatile(
        "mma.sync.aligned.m16n8k16.row.col.f32.bf16.bf16.f32 "
        "{%0,%1,%2,%3}, {%4,%5,%6,%7}, {%8,%9}, {%0,%1,%2,%3};"
        : "+f"(c[0]), "+f"(c[1]), "+f"(c[2]), "+f"(c[3])
        : "r"(a[0]), "r"(a[1]), "r"(a[2]), "r"(a[3]), "r"(b[0]), "r"(b[1]));
}
__device__ __forceinline__ uint32_t swz(uint32_t off) { return off ^ ((off >> 3) & 0x70); }

// ---- A staging: 32 k-rows x 128 m fp32 -> hi/lo bf16 tiles [k][m] ----
// tile addr(k, mbyte) = k*256 + (mbyte ^ ((k&7)<<4))
__device__ __forceinline__ void stageA(const float* __restrict__ Wbase, int ldw,
                                       uint32_t a_hi, uint32_t a_lo, int t) {
#pragma unroll
    for (int j = 0; j < 4; j++) {
        const int id = j * 1024 + t * 4;
        const int kl = id >> 7;           // 0..31
        const int m  = id & 127;          // multiple of 4
        const float4 v = *(const float4*)(Wbase + (size_t)kl * ldw + m);
        const uint32_t h0 = packbf(v.x, v.y), h1 = packbf(v.z, v.w);
        const uint32_t l0 = packbf(v.x - bflo(h0), v.y - bfhi(h0));
        const uint32_t l1 = packbf(v.z - bflo(h1), v.w - bfhi(h1));
        const uint32_t off = (uint32_t)(kl * 256) + (((uint32_t)(m * 2)) ^ ((uint32_t)(kl & 7) << 4));
        sts64(a_hi + off, h0, h1);
        sts64(a_lo + off, l0, l1);
    }
}

// ---- compute one KC=32 chunk: 2 k16-steps x 12 HMMA per warp ----
__device__ __forceinline__ void computeChunk(uint32_t buf, float acc[4][4], int L, int w) {
    const uint32_t offA0 = (uint32_t)((((L >> 4) & 1) * 8 + (L & 7)) * 256)
                         + (((uint32_t)(w * 32 + ((L >> 3) & 1) * 16)) ^ ((uint32_t)(L & 7) << 4));
    const uint32_t aHi = buf + OFF_A_HI, aLo = buf + OFF_A_LO;
    const uint32_t bHi = buf + OFF_B_HI, bLo = buf + OFF_B_LO;
#pragma unroll
    for (int ks = 0; ks < 2; ks++) {
        uint32_t ah[4], al[4], bh[8], bl[8];
        ldmA(ah, aHi + offA0 + ks * 4096);
        ldmA(al, aLo + offA0 + ks * 4096);
#pragma unroll
        for (int P = 0; P < 2; P++) {
            const uint32_t n   = (uint32_t)(P * 16 + ((L >> 4) & 1) * 8 + (L & 7));
            const uint32_t off = n * 128 +
                (((uint32_t)(ks * 32 + ((L >> 3) & 1) * 16)) ^ ((uint32_t)(L & 7) << 4));
            ldmB(bh + P * 4, bHi + off);
            ldmB(bl + P * 4, bLo + off);
        }
#pragma unroll
        for (int q = 0; q < 4; q++) {
            const uint32_t* Bh = bh + (q >> 1) * 4 + (q & 1) * 2;
            const uint32_t* Bl = bl + (q >> 1) * 4 + (q & 1) * 2;
            mma16816(acc[q], ah, Bh);
            mma16816(acc[q], ah, Bl);
            mma16816(acc[q], al, Bh);
        }
    }
}

// ============================================================
// GEMM1: D[f(128), b(32)] = sum_e W1[s][e][f0+m] * x[b][s][e] ; +b1 -> g_H packed
// grid (F/128, S), 256 threads, 3 CTAs/SM
// ============================================================
__global__ __launch_bounds__(256, 3) void k_gemm1(const float* __restrict__ x,
                                                  const float* __restrict__ W1,
                                                  const float* __restrict__ b1) {
    extern __shared__ char smraw[];
    const uint32_t sb = (s2u(smraw) + 1023u) & ~1023u;
    const int s = blockIdx.y, f0 = blockIdx.x * 128;
    const int t = threadIdx.x, w = t >> 5, L = t & 31;

    float acc[4][4];
#pragma unroll
    for (int q = 0; q < 4; q++)
#pragma unroll
        for (int r = 0; r < 4; r++) acc[q][r] = 0.f;

    auto stage = [&](int c) {
        const uint32_t buf = sb + (c & 1) * BUF_SZ;
        stageA(W1 + ((size_t)s * E_ + c * KC) * F_ + f0, F_,
               buf + OFF_A_HI, buf + OFF_A_LO, t);
        // B: x[b][s][e], [n=b][k=e], 128B row stride
#pragma unroll
        for (int i = 0; i < 2; i++) {
            const int id = i * 256 + t, b = id >> 4, ep = id & 15;
            const float2 v = *(const float2*)(x + ((size_t)b * S_ + s) * E_ + c * KC + 2 * ep);
            const uint32_t hp = packbf(v.x, v.y);
            const uint32_t lp = packbf(v.x - bflo(hp), v.y - bfhi(hp));
            const uint32_t off = swz((uint32_t)(b * 128 + ep * 4));
            sts32(buf + OFF_B_HI + off, hp);
            sts32(buf + OFF_B_LO + off, lp);
        }
    };

    stage(0);
    __syncthreads();
    const int NC = E_ / KC;                    // 16
    for (int c = 0; c < NC; c++) {
        if (c + 1 < NC) stage(c + 1);
        computeChunk(sb + (c & 1) * BUF_SZ, acc, L, w);
        __syncthreads();
    }

    // epilogue: pack hi/lo into g_H[s][b][f]
    const int fr = f0 + w * 16 + (L >> 2);
    const float bias0 = b1[s * F_ + fr];
    const float bias1 = b1[s * F_ + fr + 8];
#pragma unroll
    for (int q = 0; q < 4; q++) {
#pragma unroll
        for (int h = 0; h < 2; h++) {
#pragma unroll
            for (int p = 0; p < 2; p++) {
                const float v = acc[q][h * 2 + p] + (h ? bias1 : bias0);
                const float hv = __bfloat162float(__float2bfloat16_rn(v));
                const int b = q * 8 + (L & 3) * 2 + p;
                const int f = fr + h * 8;
                g_H[((size_t)s * B_ + b) * F_ + f] = packbf(v, v - hv);
            }
        }
    }
}

// ============================================================
// GEMM2 (k-split): D[e(128), b(32)] partial over f-half kv -> g_P[kv][b][s][e]
// grid (E/128, S, 2), 256 threads, 3 CTAs/SM
// ============================================================
__global__ __launch_bounds__(256, 3) void k_gemm2(const float* __restrict__ W2) {
    extern __shared__ char smraw[];
    const uint32_t sb = (s2u(smraw) + 1023u) & ~1023u;
    const int s = blockIdx.y, e0 = blockIdx.x * 128, kv = blockIdx.z;
    const int t = threadIdx.x, w = t >> 5, L = t & 31;
    const int c0 = kv * 32;                    // chunk offset (32 chunks per half)

    float acc[4][4];
#pragma unroll
    for (int q = 0; q < 4; q++)
#pragma unroll
        for (int r = 0; r < 4; r++) acc[q][r] = 0.f;

    auto stage = [&](int c) {
        const uint32_t buf = sb + (c & 1) * BUF_SZ;
        const int gc = c0 + c;
        stageA(W2 + ((size_t)s * F_ + gc * KC) * E_ + e0, E_,
               buf + OFF_A_HI, buf + OFF_A_LO, t);
        // B: packed H[s][b][f] -> split hi/lo
#pragma unroll
        for (int i = 0; i < 2; i++) {
            const int id = i * 256 + t, b = id >> 4, fp = id & 15;
            const uint2 u = *(const uint2*)(g_H + ((size_t)s * B_ + b) * F_ + gc * KC + 2 * fp);
            const uint32_t hp = (u.x & 0xFFFFu) | (u.y << 16);
            const uint32_t lp = (u.x >> 16) | (u.y & 0xFFFF0000u);
            const uint32_t off = swz((uint32_t)(b * 128 + fp * 4));
            sts32(buf + OFF_B_HI + off, hp);
            sts32(buf + OFF_B_LO + off, lp);
        }
    };

    stage(0);
    __syncthreads();
    const int NC = 32;                          // (F/2)/KC
    for (int c = 0; c < NC; c++) {
        if (c + 1 < NC) stage(c + 1);
        computeChunk(sb + (c & 1) * BUF_SZ, acc, L, w);
        __syncthreads();
    }

    // epilogue: raw partial -> g_P[kv][b][s][e]
    const int er = e0 + w * 16 + (L >> 2);
    float* dst = g_P[kv];
#pragma unroll
    for (int q = 0; q < 4; q++) {
#pragma unroll
        for (int h = 0; h < 2; h++) {
#pragma unroll
            for (int p = 0; p < 2; p++) {
                const int b = q * 8 + (L & 3) * 2 + p;
                const int e = er + h * 8;
                dst[((size_t)b * S_ + s) * E_ + e] = acc[q][h * 2 + p];
            }
        }
    }
}

// ============================================================
// LN: y = p0 + p1 + b2 + x; LayerNorm over E. warp per row.
// ============================================================
__global__ void k_ln(const float* __restrict__ x, const float* __restrict__ b2,
                     const float* __restrict__ gamma, const float* __restrict__ beta,
                     float* __restrict__ out) {
    const int warp = threadIdx.x >> 5, lane = threadIdx.x & 31;
    const int row  = blockIdx.x * 8 + warp;      // row = b*S + s
    const int s    = row & (S_ - 1);
    const size_t ro = (size_t)row * E_;

    float v[16];
    float sum = 0.f, sq = 0.f;
#pragma unroll
    for (int k = 0; k < 16; k++) {
        const int e = lane + 32 * k;
        const float tv = g_P[0][ro + e] + g_P[1][ro + e] + b2[s * E_ + e] + x[ro + e];
        v[k] = tv; sum += tv; sq += tv * tv;
    }
#pragma unroll
    for (int o = 16; o; o >>= 1) {
        sum += __shfl_xor_sync(0xFFFFFFFFu, sum, o);
        sq  += __shfl_xor_sync(0xFFFFFFFFu, sq,  o);
    }
    const float mu   = sum * (1.f / E_);
    const float var  = sq * (1.f / E_) - mu * mu;
    const float rstd = rsqrtf(var + 1e-5f);

    float* orow = out + ro;
#pragma unroll
    for (int k = 0; k < 16; k++) {
        const int e = lane + 32 * k;
        orow[e] = (v[k] - mu) * rstd * gamma[e] + beta[e];
    }
}

// ============================================================
extern "C" void kernel_launch(void* const* d_in, const int* in_sizes, int n_in,
                              void* d_out, int out_size) {
    const float* x     = (const float*)d_in[0];
    const float* W1    = (const float*)d_in[1];
    const float* b1    = (const float*)d_in[2];
    const float* W2    = (const float*)d_in[3];
    const float* b2    = (const float*)d_in[4];
    const float* gamma = (const float*)d_in[5];
    const float* beta  = (const float*)d_in[6];
    float* out = (float*)d_out;

    cudaFuncSetAttribute(k_gemm1, cudaFuncAttributeMaxDynamicSharedMemorySize, SM_DYN);
    cudaFuncSetAttribute(k_gemm2, cudaFuncAttributeMaxDynamicSharedMemorySize, SM_DYN);

    k_gemm1<<<dim3(F_ / 128, S_), 256, SM_DYN>>>(x, W1, b1);
    k_gemm2<<<dim3(E_ / 128, S_, 2), 256, SM_DYN>>>(W2);
    k_ln<<<(B_ * S_) / 8, 256>>>(x, b2, gamma, beta, out);
}

// round 8
// speedup vs baseline: 1.0548x; 1.0548x over previous
#include <cuda_runtime.h>
#include <cuda_bf16.h>
#include <cstdint>

static constexpr int B_ = 32, S_ = 128, E_ = 512, F_ = 2048;
static constexpr int KC = 32;    // K per chunk
static constexpr int MT = 256;   // M tile per CTA (warp tile m32 x n32)

// per-buffer SMEM: A_hi 16K | A_lo 16K | B_hi 4K | B_lo 4K
static constexpr int OFF_A_HI = 0;
static constexpr int OFF_A_LO = 16384;
static constexpr int OFF_B_HI = 32768;
static constexpr int OFF_B_LO = 36864;
static constexpr int BUF_SZ   = 40960;
static constexpr int SM_DYN   = 2 * BUF_SZ + 1024;   // 82944

// ---- scratch ----
__device__ uint32_t g_H[(size_t)S_ * B_ * F_];      // packed (hi | lo<<16) [s][b][f]
__device__ float    g_P[2][(size_t)B_ * S_ * E_];   // gemm2 k-split partials [b][s][e]

// ============ helpers ============
__device__ __forceinline__ uint32_t s2u(const void* p) {
    uint32_t a;
    asm("{ .reg .u64 t; cvta.to.shared.u64 t, %1; cvt.u32.u64 %0, t; }" : "=r"(a) : "l"(p));
    return a;
}
__device__ __forceinline__ uint32_t packbf(float lo, float hi) {   // lo -> low 16 bits
    uint32_t r; asm("cvt.rn.bf16x2.f32 %0, %1, %2;" : "=r"(r) : "f"(hi), "f"(lo)); return r;
}
__device__ __forceinline__ float bflo(uint32_t p) { return __uint_as_float(p << 16); }
__device__ __forceinline__ float bfhi(uint32_t p) { return __uint_as_float(p & 0xFFFF0000u); }
__device__ __forceinline__ void sts32(uint32_t a, uint32_t v) {
    asm volatile("st.shared.b32 [%0], %1;" :: "r"(a), "r"(v) : "memory");
}
__device__ __forceinline__ void sts64(uint32_t a, uint32_t v0, uint32_t v1) {
    asm volatile("st.shared.v2.b32 [%0], {%1, %2};" :: "r"(a), "r"(v0), "r"(v1) : "memory");
}
__device__ __forceinline__ void ldmA(uint32_t* r, uint32_t addr) {  // x4 trans: [k][m]
    asm volatile("ldmatrix.sync.aligned.m8n8.x4.trans.shared.b16 {%0,%1,%2,%3}, [%4];"
                 : "=r"(r[0]), "=r"(r[1]), "=r"(r[2]), "=r"(r[3]) : "r"(addr));
}
__device__ __forceinline__ void ldmB(uint32_t* r, uint32_t addr) {  // x4: [n][k]
    asm volatile("ldmatrix.sync.aligned.m8n8.x4.shared.b16 {%0,%1,%2,%3}, [%4];"
                 : "=r"(r[0]), "=r"(r[1]), "=r"(r[2]), "=r"(r[3]) : "r"(addr));
}
__device__ __forceinline__ void mma16816(float* c, const uint32_t* a, const uint32_t* b) {
    asm volatile(
        "mma.sync.aligned.m16n8k16.row.col.f32.bf16.bf16.f32 "
        "{%0,%1,%2,%3}, {%4,%5,%6,%7}, {%8,%9}, {%0,%1,%2,%3};"
        : "+f"(c[0]), "+f"(c[1]), "+f"(c[2]), "+f"(c[3])
        : "r"(a[0]), "r"(a[1]), "r"(a[2]), "r"(a[3]), "r"(b[0]), "r"(b[1]));
}
__device__ __forceinline__ uint32_t swz(uint32_t off) { return off ^ ((off >> 3) & 0x70); }

// ---- A staging: 32 k-rows x 256 m fp32 -> hi/lo bf16 tiles [k][m], 512B rows ----
// addr(k, mbyte) = k*512 + (mbyte ^ ((k&7)<<4))
__device__ __forceinline__ void stageA(const float* __restrict__ Wbase, int ldw,
                                       uint32_t a_hi, uint32_t a_lo, int t) {
#pragma unroll
    for (int j = 0; j < 8; j++) {
        const int id = j * 1024 + t * 4;
        const int kl = id >> 8;           // 0..31
        const int m  = id & 255;          // multiple of 4
        const float4 v = *(const float4*)(Wbase + (size_t)kl * ldw + m);
        const uint32_t h0 = packbf(v.x, v.y), h1 = packbf(v.z, v.w);
        const uint32_t l0 = packbf(v.x - bflo(h0), v.y - bfhi(h0));
        const uint32_t l1 = packbf(v.z - bflo(h1), v.w - bfhi(h1));
        const uint32_t off = (uint32_t)(kl * 512) + (((uint32_t)(m * 2)) ^ ((uint32_t)(kl & 7) << 4));
        sts64(a_hi + off, h0, h1);
        sts64(a_lo + off, l0, l1);
    }
}

// ---- one KC=32 chunk: warp tile m32 x n32, 2 k16-steps x 24 HMMA ----
__device__ __forceinline__ void computeChunk(uint32_t buf, float acc[2][4][4], int L, int w) {
    const uint32_t rowA = (uint32_t)((((L >> 4) & 1) * 8 + (L & 7)) * 512);
    const uint32_t aHi = buf + OFF_A_HI, aLo = buf + OFF_A_LO;
    const uint32_t bHi = buf + OFF_B_HI, bLo = buf + OFF_B_LO;
#pragma unroll
    for (int ks = 0; ks < 2; ks++) {
        uint32_t bh[8], bl[8];
#pragma unroll
        for (int P = 0; P < 2; P++) {
            const uint32_t n   = (uint32_t)(P * 16 + ((L >> 4) & 1) * 8 + (L & 7));
            const uint32_t off = n * 128 +
                (((uint32_t)(ks * 32 + ((L >> 3) & 1) * 16)) ^ ((uint32_t)(L & 7) << 4));
            ldmB(bh + P * 4, bHi + off);
            ldmB(bl + P * 4, bLo + off);
        }
#pragma unroll
        for (int mt = 0; mt < 2; mt++) {
            uint32_t ah[4], al[4];
            const uint32_t colA = ((uint32_t)(w * 64 + mt * 32 + ((L >> 3) & 1) * 16))
                                  ^ ((uint32_t)(L & 7) << 4);
            ldmA(ah, aHi + rowA + (uint32_t)(ks * 8192) + colA);
            ldmA(al, aLo + rowA + (uint32_t)(ks * 8192) + colA);
#pragma unroll
            for (int q = 0; q < 4; q++) {
                const uint32_t* Bh = bh + (q >> 1) * 4 + (q & 1) * 2;
                const uint32_t* Bl = bl + (q >> 1) * 4 + (q & 1) * 2;
                mma16816(acc[mt][q], ah, Bh);
                mma16816(acc[mt][q], ah, Bl);
                mma16816(acc[mt][q], al, Bh);
            }
        }
    }
}

// ============================================================
// GEMM1: D[f(256), b(32)] = sum_e W1[s][e][f0+m] * x[b][s][e] ; +b1 -> g_H packed
// grid (F/256, S), 256 threads, 2 CTAs/SM
// ============================================================
__global__ __launch_bounds__(256, 2) void k_gemm1(const float* __restrict__ x,
                                                  const float* __restrict__ W1,
                                                  const float* __restrict__ b1) {
    extern __shared__ char smraw[];
    const uint32_t sb = (s2u(smraw) + 1023u) & ~1023u;
    const int s = blockIdx.y, f0 = blockIdx.x * MT;
    const int t = threadIdx.x, w = t >> 5, L = t & 31;

    float acc[2][4][4];
#pragma unroll
    for (int mt = 0; mt < 2; mt++)
#pragma unroll
        for (int q = 0; q < 4; q++)
#pragma unroll
            for (int r = 0; r < 4; r++) acc[mt][q][r] = 0.f;

    auto stage = [&](int c) {
        const uint32_t buf = sb + (c & 1) * BUF_SZ;
        stageA(W1 + ((size_t)s * E_ + c * KC) * F_ + f0, F_,
               buf + OFF_A_HI, buf + OFF_A_LO, t);
        // B: x[b][s][e], [n=b][k=e], 128B row stride
#pragma unroll
        for (int i = 0; i < 2; i++) {
            const int id = i * 256 + t, b = id >> 4, ep = id & 15;
            const float2 v = *(const float2*)(x + ((size_t)b * S_ + s) * E_ + c * KC + 2 * ep);
            const uint32_t hp = packbf(v.x, v.y);
            const uint32_t lp = packbf(v.x - bflo(hp), v.y - bfhi(hp));
            const uint32_t off = swz((uint32_t)(b * 128 + ep * 4));
            sts32(buf + OFF_B_HI + off, hp);
            sts32(buf + OFF_B_LO + off, lp);
        }
    };

    stage(0);
    __syncthreads();
    const int NC = E_ / KC;                    // 16
    for (int c = 0; c < NC; c++) {
        if (c + 1 < NC) stage(c + 1);
        computeChunk(sb + (c & 1) * BUF_SZ, acc, L, w);
        __syncthreads();
    }

    // epilogue: pack hi/lo into g_H[s][b][f]
#pragma unroll
    for (int mt = 0; mt < 2; mt++) {
        const int fr = f0 + w * 32 + mt * 16 + (L >> 2);
        const float bias0 = b1[s * F_ + fr];
        const float bias1 = b1[s * F_ + fr + 8];
#pragma unroll
        for (int q = 0; q < 4; q++) {
#pragma unroll
            for (int h = 0; h < 2; h++) {
#pragma unroll
                for (int p = 0; p < 2; p++) {
                    const float v = acc[mt][q][h * 2 + p] + (h ? bias1 : bias0);
                    const float hv = __bfloat162float(__float2bfloat16_rn(v));
                    const int b = q * 8 + (L & 3) * 2 + p;
                    const int f = fr + h * 8;
                    g_H[((size_t)s * B_ + b) * F_ + f] = packbf(v, v - hv);
                }
            }
        }
    }
}

// ============================================================
// GEMM2 (k-split): D[e(256), b(32)] partial over f-half kv -> g_P[kv][b][s][e]
// grid (E/256, S, 2), 256 threads, 2 CTAs/SM
// ============================================================
__global__ __launch_bounds__(256, 2) void k_gemm2(const float* __restrict__ W2) {
    extern __shared__ char smraw[];
    const uint32_t sb = (s2u(smraw) + 1023u) & ~1023u;
    const int s = blockIdx.y, e0 = blockIdx.x * MT, kv = blockIdx.z;
    const int t = threadIdx.x, w = t >> 5, L = t & 31;
    const int c0 = kv * 32;                    // 32 chunks per half

    float acc[2][4][4];
#pragma unroll
    for (int mt = 0; mt < 2; mt++)
#pragma unroll
        for (int q = 0; q < 4; q++)
#pragma unroll
            for (int r = 0; r < 4; r++) acc[mt][q][r] = 0.f;

    auto stage = [&](int c) {
        const uint32_t buf = sb + (c & 1) * BUF_SZ;
        const int gc = c0 + c;
        stageA(W2 + ((size_t)s * F_ + gc * KC) * E_ + e0, E_,
               buf + OFF_A_HI, buf + OFF_A_LO, t);
        // B: packed H[s][b][f] -> split hi/lo
#pragma unroll
        for (int i = 0; i < 2; i++) {
            const int id = i * 256 + t, b = id >> 4, fp = id & 15;
            const uint2 u = *(const uint2*)(g_H + ((size_t)s * B_ + b) * F_ + gc * KC + 2 * fp);
            const uint32_t hp = (u.x & 0xFFFFu) | (u.y << 16);
            const uint32_t lp = (u.x >> 16) | (u.y & 0xFFFF0000u);
            const uint32_t off = swz((uint32_t)(b * 128 + fp * 4));
            sts32(buf + OFF_B_HI + off, hp);
            sts32(buf + OFF_B_LO + off, lp);
        }
    };

    stage(0);
    __syncthreads();
    const int NC = 32;                          // (F/2)/KC
    for (int c = 0; c < NC; c++) {
        if (c + 1 < NC) stage(c + 1);
        computeChunk(sb + (c & 1) * BUF_SZ, acc, L, w);
        __syncthreads();
    }

    // epilogue: raw partial -> g_P[kv][b][s][e]
    float* dst = g_P[kv];
#pragma unroll
    for (int mt = 0; mt < 2; mt++) {
        const int er = e0 + w * 32 + mt * 16 + (L >> 2);
#pragma unroll
        for (int q = 0; q < 4; q++) {
#pragma unroll
            for (int h = 0; h < 2; h++) {
#pragma unroll
                for (int p = 0; p < 2; p++) {
                    const int b = q * 8 + (L & 3) * 2 + p;
                    const int e = er + h * 8;
                    dst[((size_t)b * S_ + s) * E_ + e] = acc[mt][q][h * 2 + p];
                }
            }
        }
    }
}

// ============================================================
// LN: y = p0 + p1 + b2 + x; LayerNorm over E. warp per row.
// ============================================================
__global__ void k_ln(const float* __restrict__ x, const float* __restrict__ b2,
                     const float* __restrict__ gamma, const float* __restrict__ beta,
                     float* __restrict__ out) {
    const int warp = threadIdx.x >> 5, lane = threadIdx.x & 31;
    const int row  = blockIdx.x * 8 + warp;      // row = b*S + s
    const int s    = row & (S_ - 1);
    const size_t ro = (size_t)row * E_;

    float v[16];
    float sum = 0.f, sq = 0.f;
#pragma unroll
    for (int k = 0; k < 16; k++) {
        const int e = lane + 32 * k;
        const float tv = g_P[0][ro + e] + g_P[1][ro + e] + b2[s * E_ + e] + x[ro + e];
        v[k] = tv; sum += tv; sq += tv * tv;
    }
#pragma unroll
    for (int o = 16; o; o >>= 1) {
        sum += __shfl_xor_sync(0xFFFFFFFFu, sum, o);
        sq  += __shfl_xor_sync(0xFFFFFFFFu, sq,  o);
    }
    const float mu   = sum * (1.f / E_);
    const float var  = sq * (1.f / E_) - mu * mu;
    const float rstd = rsqrtf(var + 1e-5f);

    float* orow = out + ro;
#pragma unroll
    for (int k = 0; k < 16; k++) {
        const int e = lane + 32 * k;
        orow[e] = (v[k] - mu) * rstd * gamma[e] + beta[e];
    }
}

// ============================================================
extern "C" void kernel_launch(void* const* d_in, const int* in_sizes, int n_in,
                              void* d_out, int out_size) {
    const float* x     = (const float*)d_in[0];
    const float* W1    = (const float*)d_in[1];
    const float* b1    = (const float*)d_in[2];
    const float* W2    = (const float*)d_in[3];
    const float* b2    = (const float*)d_in[4];
    const float* gamma = (const float*)d_in[5];
    const float* beta  = (const float*)d_in[6];
    float* out = (float*)d_out;

    cudaFuncSetAttribute(k_gemm1, cudaFuncAttributeMaxDynamicSharedMemorySize, SM_DYN);
    cudaFuncSetAttribute(k_gemm2, cudaFuncAttributeMaxDynamicSharedMemorySize, SM_DYN);

    k_gemm1<<<dim3(F_ / MT, S_), 256, SM_DYN>>>(x, W1, b1);
    k_gemm2<<<dim3(E_ / MT, S_, 2), 256, SM_DYN>>>(W2);
    k_ln<<<(B_ * S_) / 8, 256>>>(x, b2, gamma, beta, out);
}

// round 9
// speedup vs baseline: 1.2016x; 1.1392x over previous
#include <cuda_runtime.h>
#include <cuda_bf16.h>
#include <cstdint>

static constexpr int B_ = 32, S_ = 128, E_ = 512, F_ = 2048;
static constexpr int KC = 32;    // K per chunk
static constexpr int MT = 256;   // M tile per CTA (warp tile m32 x n32)

// SMEM: bf16 tiles (single buffer) then fp32 A stage (double buffer)
static constexpr int OFF_A_HI = 0;
static constexpr int OFF_A_LO = 16384;
static constexpr int OFF_B_HI = 32768;
static constexpr int OFF_B_LO = 36864;
static constexpr int OFF_ST   = 40960;           // 2 x 32768 fp32 A stage
static constexpr int SM_DYN   = 40960 + 65536 + 1024;   // 107520 -> 2 CTAs/SM

// ---- scratch ----
__device__ uint32_t g_H[(size_t)S_ * B_ * F_];      // packed (hi | lo<<16) [s][b][f]
__device__ float    g_P[2][(size_t)B_ * S_ * E_];   // gemm2 k-split partials [b][s][e]

// ============ helpers ============
__device__ __forceinline__ uint32_t s2u(const void* p) {
    uint32_t a;
    asm("{ .reg .u64 t; cvta.to.shared.u64 t, %1; cvt.u32.u64 %0, t; }" : "=r"(a) : "l"(p));
    return a;
}
__device__ __forceinline__ uint32_t packbf(float lo, float hi) {   // lo -> low 16 bits
    uint32_t r; asm("cvt.rn.bf16x2.f32 %0, %1, %2;" : "=r"(r) : "f"(hi), "f"(lo)); return r;
}
__device__ __forceinline__ float bflo(uint32_t p) { return __uint_as_float(p << 16); }
__device__ __forceinline__ float bfhi(uint32_t p) { return __uint_as_float(p & 0xFFFF0000u); }
__device__ __forceinline__ void sts32(uint32_t a, uint32_t v) {
    asm volatile("st.shared.b32 [%0], %1;" :: "r"(a), "r"(v) : "memory");
}
__device__ __forceinline__ void sts64(uint32_t a, uint32_t v0, uint32_t v1) {
    asm volatile("st.shared.v2.b32 [%0], {%1, %2};" :: "r"(a), "r"(v0), "r"(v1) : "memory");
}
__device__ __forceinline__ void lds128(float4& v, uint32_t a) {
    asm volatile("ld.shared.v4.f32 {%0,%1,%2,%3}, [%4];"
                 : "=f"(v.x), "=f"(v.y), "=f"(v.z), "=f"(v.w) : "r"(a));
}
__device__ __forceinline__ void cpasync16(uint32_t saddr, const void* g) {
    asm volatile("cp.async.cg.shared.global [%0], [%1], 16;" :: "r"(saddr), "l"(g) : "memory");
}
__device__ __forceinline__ void cp_commit() {
    asm volatile("cp.async.commit_group;" ::: "memory");
}
__device__ __forceinline__ void cp_wait1() {
    asm volatile("cp.async.wait_group 1;" ::: "memory");
}
__device__ __forceinline__ void ldmA(uint32_t* r, uint32_t addr) {  // x4 trans: [k][m]
    asm volatile("ldmatrix.sync.aligned.m8n8.x4.trans.shared.b16 {%0,%1,%2,%3}, [%4];"
                 : "=r"(r[0]), "=r"(r[1]), "=r"(r[2]), "=r"(r[3]) : "r"(addr));
}
__device__ __forceinline__ void ldmB(uint32_t* r, uint32_t addr) {  // x4: [n][k]
    asm volatile("ldmatrix.sync.aligned.m8n8.x4.shared.b16 {%0,%1,%2,%3}, [%4];"
                 : "=r"(r[0]), "=r"(r[1]), "=r"(r[2]), "=r"(r[3]) : "r"(addr));
}
__device__ __forceinline__ void mma16816(float* c, const uint32_t* a, const uint32_t* b) {
    asm volatile(
        "mma.sync.aligned.m16n8k16.row.col.f32.bf16.bf16.f32 "
        "{%0,%1,%2,%3}, {%4,%5,%6,%7}, {%8,%9}, {%0,%1,%2,%3};"
        : "+f"(c[0]), "+f"(c[1]), "+f"(c[2]), "+f"(c[3])
        : "r"(a[0]), "r"(a[1]), "r"(a[2]), "r"(a[3]), "r"(b[0]), "r"(b[1]));
}
__device__ __forceinline__ uint32_t swz(uint32_t off) { return off ^ ((off >> 3) & 0x70); }

// ---- cp.async: raw fp32 A chunk (32 k-rows x 256 m) -> linear stage buffer ----
__device__ __forceinline__ void cpA(const float* __restrict__ base, int ldw,
                                    uint32_t st, int t) {
#pragma unroll
    for (int j = 0; j < 8; j++) {
        const int id = j * 256 + t;          // 16B units
        const int kl = id >> 6, ir = id & 63;
        cpasync16(st + (uint32_t)id * 16, base + (size_t)kl * ldw + ir * 4);
    }
    cp_commit();
}

// ---- convert: fp32 stage -> hi/lo bf16 tiles [k][m], 512B rows ----
__device__ __forceinline__ void convA(uint32_t st, uint32_t a_hi, uint32_t a_lo, int t) {
#pragma unroll
    for (int j = 0; j < 8; j++) {
        const int id = j * 1024 + t * 4;
        const int kl = id >> 8, m = id & 255;
        float4 v; lds128(v, st + (uint32_t)id * 4);
        const uint32_t h0 = packbf(v.x, v.y), h1 = packbf(v.z, v.w);
        const uint32_t l0 = packbf(v.x - bflo(h0), v.y - bfhi(h0));
        const uint32_t l1 = packbf(v.z - bflo(h1), v.w - bfhi(h1));
        const uint32_t off = (uint32_t)(kl * 512) + (((uint32_t)(m * 2)) ^ ((uint32_t)(kl & 7) << 4));
        sts64(a_hi + off, h0, h1);
        sts64(a_lo + off, l0, l1);
    }
}

// ---- one KC=32 chunk: warp tile m32 x n32, 2 k16-steps x 24 HMMA ----
__device__ __forceinline__ void computeChunk(uint32_t buf, float acc[2][4][4], int L, int w) {
    const uint32_t rowA = (uint32_t)((((L >> 4) & 1) * 8 + (L & 7)) * 512);
    const uint32_t aHi = buf + OFF_A_HI, aLo = buf + OFF_A_LO;
    const uint32_t bHi = buf + OFF_B_HI, bLo = buf + OFF_B_LO;
#pragma unroll
    for (int ks = 0; ks < 2; ks++) {
        uint32_t bh[8], bl[8];
#pragma unroll
        for (int P = 0; P < 2; P++) {
            const uint32_t n   = (uint32_t)(P * 16 + ((L >> 4) & 1) * 8 + (L & 7));
            const uint32_t off = n * 128 +
                (((uint32_t)(ks * 32 + ((L >> 3) & 1) * 16)) ^ ((uint32_t)(L & 7) << 4));
            ldmB(bh + P * 4, bHi + off);
            ldmB(bl + P * 4, bLo + off);
        }
#pragma unroll
        for (int mt = 0; mt < 2; mt++) {
            uint32_t ah[4], al[4];
            const uint32_t colA = ((uint32_t)(w * 64 + mt * 32 + ((L >> 3) & 1) * 16))
                                  ^ ((uint32_t)(L & 7) << 4);
            ldmA(ah, aHi + rowA + (uint32_t)(ks * 8192) + colA);
            ldmA(al, aLo + rowA + (uint32_t)(ks * 8192) + colA);
#pragma unroll
            for (int q = 0; q < 4; q++) {
                const uint32_t* Bh = bh + (q >> 1) * 4 + (q & 1) * 2;
                const uint32_t* Bl = bl + (q >> 1) * 4 + (q & 1) * 2;
                mma16816(acc[mt][q], ah, Bh);
                mma16816(acc[mt][q], ah, Bl);
                mma16816(acc[mt][q], al, Bh);
            }
        }
    }
}

// ============================================================
// GEMM1: D[f(256), b(32)] = sum_e W1[s][e][f0+m] * x[b][s][e] ; +b1 -> g_H packed
// grid (F/256, S), 256 threads, 2 CTAs/SM
// ============================================================
__global__ __launch_bounds__(256, 2) void k_gemm1(const float* __restrict__ x,
                                                  const float* __restrict__ W1,
                                                  const float* __restrict__ b1) {
    extern __shared__ char smraw[];
    const uint32_t sb = (s2u(smraw) + 1023u) & ~1023u;
    const int s = blockIdx.y, f0 = blockIdx.x * MT;
    const int t = threadIdx.x, w = t >> 5, L = t & 31;

    float acc[2][4][4];
#pragma unroll
    for (int mt = 0; mt < 2; mt++)
#pragma unroll
        for (int q = 0; q < 4; q++)
#pragma unroll
            for (int r = 0; r < 4; r++) acc[mt][q][r] = 0.f;

    const float* Wb = W1 + (size_t)s * E_ * F_ + f0;
    const int bi = t >> 4, ep0 = (t & 15) * 2;       // B prefetch mapping (i=0: b=bi, i=1: b=bi+16)

    auto ldB = [&](int c, float2* rb) {
#pragma unroll
        for (int i = 0; i < 2; i++)
            rb[i] = *(const float2*)(x + ((size_t)(bi + i * 16) * S_ + s) * E_ + c * KC + ep0);
    };
    auto stsB = [&](const float2* rb) {
#pragma unroll
        for (int i = 0; i < 2; i++) {
            const uint32_t hp = packbf(rb[i].x, rb[i].y);
            const uint32_t lp = packbf(rb[i].x - bflo(hp), rb[i].y - bfhi(hp));
            const uint32_t off = swz((uint32_t)((bi + i * 16) * 128 + ep0 * 2));
            sts32(sb + OFF_B_HI + off, hp);
            sts32(sb + OFF_B_LO + off, lp);
        }
    };

    float2 rb[2];
    cpA(Wb, F_, sb + OFF_ST, t);
    ldB(0, rb);
    cpA(Wb + (size_t)KC * F_, F_, sb + OFF_ST + 32768, t);

    const int NC = E_ / KC;                    // 16
    for (int c = 0; c < NC; c++) {
        cp_wait1();
        __syncthreads();                       // bf16 tiles free + stage c visible
        stsB(rb);
        if (c + 1 < NC) ldB(c + 1, rb);
        convA(sb + OFF_ST + (c & 1) * 32768, sb + OFF_A_HI, sb + OFF_A_LO, t);
        __syncthreads();                       // tiles ready; stage (c&1) free
        if (c + 2 < NC) cpA(Wb + (size_t)(c + 2) * KC * F_, F_, sb + OFF_ST + (c & 1) * 32768, t);
        computeChunk(sb, acc, L, w);
    }

    // epilogue: pack hi/lo into g_H[s][b][f]
#pragma unroll
    for (int mt = 0; mt < 2; mt++) {
        const int fr = f0 + w * 32 + mt * 16 + (L >> 2);
        const float bias0 = b1[s * F_ + fr];
        const float bias1 = b1[s * F_ + fr + 8];
#pragma unroll
        for (int q = 0; q < 4; q++) {
#pragma unroll
            for (int h = 0; h < 2; h++) {
#pragma unroll
                for (int p = 0; p < 2; p++) {
                    const float v = acc[mt][q][h * 2 + p] + (h ? bias1 : bias0);
                    const float hv = __bfloat162float(__float2bfloat16_rn(v));
                    const int b = q * 8 + (L & 3) * 2 + p;
                    const int f = fr + h * 8;
                    g_H[((size_t)s * B_ + b) * F_ + f] = packbf(v, v - hv);
                }
            }
        }
    }
}

// ============================================================
// GEMM2 (k-split): D[e(256), b(32)] partial over f-half kv -> g_P[kv][b][s][e]
// grid (E/256, S, 2), 256 threads, 2 CTAs/SM
// ============================================================
__global__ __launch_bounds__(256, 2) void k_gemm2(const float* __restrict__ W2) {
    extern __shared__ char smraw[];
    const uint32_t sb = (s2u(smraw) + 1023u) & ~1023u;
    const int s = blockIdx.y, e0 = blockIdx.x * MT, kv = blockIdx.z;
    const int t = threadIdx.x, w = t >> 5, L = t & 31;

    float acc[2][4][4];
#pragma unroll
    for (int mt = 0; mt < 2; mt++)
#pragma unroll
        for (int q = 0; q < 4; q++)
#pragma unroll
            for (int r = 0; r < 4; r++) acc[mt][q][r] = 0.f;

    const float* Wb = W2 + ((size_t)s * F_ + kv * (F_ / 2)) * E_ + e0;
    const int f_base = kv * (F_ / 2);
    const int bi = t >> 4, fp0 = (t & 15) * 2;

    auto ldB = [&](int c, uint2* rb) {
#pragma unroll
        for (int i = 0; i < 2; i++)
            rb[i] = *(const uint2*)(g_H + ((size_t)s * B_ + bi + i * 16) * F_
                                    + f_base + c * KC + fp0);
    };
    auto stsB = [&](const uint2* rb) {
#pragma unroll
        for (int i = 0; i < 2; i++) {
            const uint32_t hp = (rb[i].x & 0xFFFFu) | (rb[i].y << 16);
            const uint32_t lp = (rb[i].x >> 16) | (rb[i].y & 0xFFFF0000u);
            const uint32_t off = swz((uint32_t)((bi + i * 16) * 128 + fp0 * 2));
            sts32(sb + OFF_B_HI + off, hp);
            sts32(sb + OFF_B_LO + off, lp);
        }
    };

    uint2 rb[2];
    cpA(Wb, E_, sb + OFF_ST, t);
    ldB(0, rb);
    cpA(Wb + (size_t)KC * E_, E_, sb + OFF_ST + 32768, t);

    const int NC = (F_ / 2) / KC;              // 32
    for (int c = 0; c < NC; c++) {
        cp_wait1();
        __syncthreads();
        stsB(rb);
        if (c + 1 < NC) ldB(c + 1, rb);
        convA(sb + OFF_ST + (c & 1) * 32768, sb + OFF_A_HI, sb + OFF_A_LO, t);
        __syncthreads();
        if (c + 2 < NC) cpA(Wb + (size_t)(c + 2) * KC * E_, E_, sb + OFF_ST + (c & 1) * 32768, t);
        computeChunk(sb, acc, L, w);
    }

    // epilogue: raw partial -> g_P[kv][b][s][e]
    float* dst = g_P[kv];
#pragma unroll
    for (int mt = 0; mt < 2; mt++) {
        const int er = e0 + w * 32 + mt * 16 + (L >> 2);
#pragma unroll
        for (int q = 0; q < 4; q++) {
#pragma unroll
            for (int h = 0; h < 2; h++) {
#pragma unroll
                for (int p = 0; p < 2; p++) {
                    const int b = q * 8 + (L & 3) * 2 + p;
                    const int e = er + h * 8;
                    dst[((size_t)b * S_ + s) * E_ + e] = acc[mt][q][h * 2 + p];
                }
            }
        }
    }
}

// ============================================================
// LN: y = p0 + p1 + b2 + x; LayerNorm over E. warp per row.
// ============================================================
__global__ void k_ln(const float* __restrict__ x, const float* __restrict__ b2,
                     const float* __restrict__ gamma, const float* __restrict__ beta,
                     float* __restrict__ out) {
    const int warp = threadIdx.x >> 5, lane = threadIdx.x & 31;
    const int row  = blockIdx.x * 8 + warp;      // row = b*S + s
    const int s    = row & (S_ - 1);
    const size_t ro = (size_t)row * E_;

    float v[16];
    float sum = 0.f, sq = 0.f;
#pragma unroll
    for (int k = 0; k < 16; k++) {
        const int e = lane + 32 * k;
        const float tv = g_P[0][ro + e] + g_P[1][ro + e] + b2[s * E_ + e] + x[ro + e];
        v[k] = tv; sum += tv; sq += tv * tv;
    }
#pragma unroll
    for (int o = 16; o; o >>= 1) {
        sum += __shfl_xor_sync(0xFFFFFFFFu, sum, o);
        sq  += __shfl_xor_sync(0xFFFFFFFFu, sq,  o);
    }
    const float mu   = sum * (1.f / E_);
    const float var  = sq * (1.f / E_) - mu * mu;
    const float rstd = rsqrtf(var + 1e-5f);

    float* orow = out + ro;
#pragma unroll
    for (int k = 0; k < 16; k++) {
        const int e = lane + 32 * k;
        orow[e] = (v[k] - mu) * rstd * gamma[e] + beta[e];
    }
}

// ============================================================
extern "C" void kernel_launch(void* const* d_in, const int* in_sizes, int n_in,
                              void* d_out, int out_size) {
    const float* x     = (const float*)d_in[0];
    const float* W1    = (const float*)d_in[1];
    const float* b1    = (const float*)d_in[2];
    const float* W2    = (const float*)d_in[3];
    const float* b2    = (const float*)d_in[4];
    const float* gamma = (const float*)d_in[5];
    const float* beta  = (const float*)d_in[6];
    float* out = (float*)d_out;

    cudaFuncSetAttribute(k_gemm1, cudaFuncAttributeMaxDynamicSharedMemorySize, SM_DYN);
    cudaFuncSetAttribute(k_gemm2, cudaFuncAttributeMaxDynamicSharedMemorySize, SM_DYN);

    k_gemm1<<<dim3(F_ / MT, S_), 256, SM_DYN>>>(x, W1, b1);
    k_gemm2<<<dim3(E_ / MT, S_, 2), 256, SM_DYN>>>(W2);
    k_ln<<<(B_ * S_) / 8, 256>>>(x, b2, gamma, beta, out);
}

// round 10
// speedup vs baseline: 1.2826x; 1.0674x over previous
#include <cuda_runtime.h>
#include <cuda_bf16.h>
#include <cstdint>

static constexpr int B_ = 32, S_ = 128, E_ = 512, F_ = 2048;
static constexpr int KC = 32;    // K per chunk
static constexpr int MT = 256;   // M tile per CTA (warp tile m32 x n32)

// SMEM: B bf16 tiles | 3-deep fp32 A stage ring
static constexpr int OFF_B_HI = 0;
static constexpr int OFF_B_LO = 4096;
static constexpr int OFF_ST   = 8192;
static constexpr int STG_SZ   = 32768;           // 32 k-rows x 256 m fp32
static constexpr int SM_DYN   = 8192 + 3 * STG_SZ + 1024;   // 107520 -> 2 CTAs/SM

// ---- scratch ----
__device__ uint32_t g_H[(size_t)S_ * B_ * F_];      // packed (hi | lo<<16) [s][b][f]
__device__ float    g_P[2][(size_t)B_ * S_ * E_];   // gemm2 k-split partials [b][s][e]

// ============ helpers ============
__device__ __forceinline__ uint32_t s2u(const void* p) {
    uint32_t a;
    asm("{ .reg .u64 t; cvta.to.shared.u64 t, %1; cvt.u32.u64 %0, t; }" : "=r"(a) : "l"(p));
    return a;
}
__device__ __forceinline__ uint32_t packbf(float lo, float hi) {   // lo -> low 16 bits
    uint32_t r; asm("cvt.rn.bf16x2.f32 %0, %1, %2;" : "=r"(r) : "f"(hi), "f"(lo)); return r;
}
__device__ __forceinline__ float bflo(uint32_t p) { return __uint_as_float(p << 16); }
__device__ __forceinline__ float bfhi(uint32_t p) { return __uint_as_float(p & 0xFFFF0000u); }
__device__ __forceinline__ void sts32(uint32_t a, uint32_t v) {
    asm volatile("st.shared.b32 [%0], %1;" :: "r"(a), "r"(v) : "memory");
}
__device__ __forceinline__ float ldsf(uint32_t a) {
    float v; asm volatile("ld.shared.f32 %0, [%1];" : "=f"(v) : "r"(a)); return v;
}
__device__ __forceinline__ void cpasync16(uint32_t saddr, const void* g) {
    asm volatile("cp.async.cg.shared.global [%0], [%1], 16;" :: "r"(saddr), "l"(g) : "memory");
}
__device__ __forceinline__ void cp_commit() {
    asm volatile("cp.async.commit_group;" ::: "memory");
}
__device__ __forceinline__ void cp_wait2() {
    asm volatile("cp.async.wait_group 2;" ::: "memory");
}
__device__ __forceinline__ void ldmB(uint32_t* r, uint32_t addr) {  // x4: [n][k]
    asm volatile("ldmatrix.sync.aligned.m8n8.x4.shared.b16 {%0,%1,%2,%3}, [%4];"
                 : "=r"(r[0]), "=r"(r[1]), "=r"(r[2]), "=r"(r[3]) : "r"(addr));
}
__device__ __forceinline__ void mma16816(float* c, const uint32_t* a, const uint32_t* b) {
    asm volatile(
        "mma.sync.aligned.m16n8k16.row.col.f32.bf16.bf16.f32 "
        "{%0,%1,%2,%3}, {%4,%5,%6,%7}, {%8,%9}, {%0,%1,%2,%3};"
        : "+f"(c[0]), "+f"(c[1]), "+f"(c[2]), "+f"(c[3])
        : "r"(a[0]), "r"(a[1]), "r"(a[2]), "r"(a[3]), "r"(b[0]), "r"(b[1]));
}
__device__ __forceinline__ uint32_t swz(uint32_t off) { return off ^ ((off >> 3) & 0x70); }

// fp32 A stage addressing: [k][m], 1KB rows, XOR swizzle
__device__ __forceinline__ uint32_t a_addr(int k, int m) {
    return (uint32_t)(k * 1024) + (((uint32_t)(m * 4)) ^ ((uint32_t)(k & 7) << 4));
}

// ---- cp.async: raw fp32 A chunk (32 k-rows x 256 m) -> swizzled stage ----
__device__ __forceinline__ void cpA(const float* __restrict__ base, int ldw,
                                    uint32_t st, int t) {
#pragma unroll
    for (int j = 0; j < 8; j++) {
        const int id = j * 256 + t;          // 16B units
        const int kl = id >> 6, ir = id & 63;
        const uint32_t sa = st + (uint32_t)(kl * 1024)
                          + (((uint32_t)(ir * 16)) ^ ((uint32_t)(kl & 7) << 4));
        cpasync16(sa, base + (size_t)kl * ldw + ir * 4);
    }
    cp_commit();
}

// ---- build one m16k16 A fragment (hi/lo) straight from fp32 stage ----
__device__ __forceinline__ void loadAfrag(uint32_t st, int m_r, int k_c,
                                          uint32_t* ah, uint32_t* al) {
    float v0 = ldsf(st + a_addr(k_c,     m_r));
    float v1 = ldsf(st + a_addr(k_c + 1, m_r));
    float v2 = ldsf(st + a_addr(k_c,     m_r + 8));
    float v3 = ldsf(st + a_addr(k_c + 1, m_r + 8));
    float v4 = ldsf(st + a_addr(k_c + 8, m_r));
    float v5 = ldsf(st + a_addr(k_c + 9, m_r));
    float v6 = ldsf(st + a_addr(k_c + 8, m_r + 8));
    float v7 = ldsf(st + a_addr(k_c + 9, m_r + 8));
    ah[0] = packbf(v0, v1); ah[1] = packbf(v2, v3);
    ah[2] = packbf(v4, v5); ah[3] = packbf(v6, v7);
    al[0] = packbf(v0 - bflo(ah[0]), v1 - bfhi(ah[0]));
    al[1] = packbf(v2 - bflo(ah[1]), v3 - bfhi(ah[1]));
    al[2] = packbf(v4 - bflo(ah[2]), v5 - bfhi(ah[2]));
    al[3] = packbf(v6 - bflo(ah[3]), v7 - bfhi(ah[3]));
}

// ---- one KC=32 chunk: warp tile m32 x n32, A from fp32 stage, B from bf16 tiles ----
__device__ __forceinline__ void computeChunk(uint32_t sb, uint32_t st,
                                             float acc[2][4][4], int L, int w) {
    const uint32_t bHi = sb + OFF_B_HI, bLo = sb + OFF_B_LO;
#pragma unroll
    for (int ks = 0; ks < 2; ks++) {
        uint32_t bh[8], bl[8];
#pragma unroll
        for (int P = 0; P < 2; P++) {
            const uint32_t n   = (uint32_t)(P * 16 + ((L >> 4) & 1) * 8 + (L & 7));
            const uint32_t off = n * 128 +
                (((uint32_t)(ks * 32 + ((L >> 3) & 1) * 16)) ^ ((uint32_t)(L & 7) << 4));
            ldmB(bh + P * 4, bHi + off);
            ldmB(bl + P * 4, bLo + off);
        }
#pragma unroll
        for (int mt = 0; mt < 2; mt++) {
            uint32_t ah[4], al[4];
            loadAfrag(st, w * 32 + mt * 16 + (L >> 2), ks * 16 + (L & 3) * 2, ah, al);
#pragma unroll
            for (int q = 0; q < 4; q++) {
                const uint32_t* Bh = bh + (q >> 1) * 4 + (q & 1) * 2;
                const uint32_t* Bl = bl + (q >> 1) * 4 + (q & 1) * 2;
                mma16816(acc[mt][q], ah, Bh);
                mma16816(acc[mt][q], ah, Bl);
                mma16816(acc[mt][q], al, Bh);
            }
        }
    }
}

// ============================================================
// GEMM1: D[f(256), b(32)] = sum_e W1[s][e][f0+m] * x[b][s][e] ; +b1 -> g_H packed
// grid (F/256, S), 256 threads, 2 CTAs/SM
// ============================================================
__global__ __launch_bounds__(256, 2) void k_gemm1(const float* __restrict__ x,
                                                  const float* __restrict__ W1,
                                                  const float* __restrict__ b1) {
    extern __shared__ char smraw[];
    const uint32_t sb = (s2u(smraw) + 1023u) & ~1023u;
    const int s = blockIdx.y, f0 = blockIdx.x * MT;
    const int t = threadIdx.x, w = t >> 5, L = t & 31;

    float acc[2][4][4];
#pragma unroll
    for (int mt = 0; mt < 2; mt++)
#pragma unroll
        for (int q = 0; q < 4; q++)
#pragma unroll
            for (int r = 0; r < 4; r++) acc[mt][q][r] = 0.f;

    const float* Wb = W1 + (size_t)s * E_ * F_ + f0;
    const int bi = t >> 4, ep0 = (t & 15) * 2;

    auto ldB = [&](int c, float2* rb) {
#pragma unroll
        for (int i = 0; i < 2; i++)
            rb[i] = *(const float2*)(x + ((size_t)(bi + i * 16) * S_ + s) * E_ + c * KC + ep0);
    };
    auto stsB = [&](const float2* rb) {
#pragma unroll
        for (int i = 0; i < 2; i++) {
            const uint32_t hp = packbf(rb[i].x, rb[i].y);
            const uint32_t lp = packbf(rb[i].x - bflo(hp), rb[i].y - bfhi(hp));
            const uint32_t off = swz((uint32_t)((bi + i * 16) * 128 + ep0 * 2));
            sts32(sb + OFF_B_HI + off, hp);
            sts32(sb + OFF_B_LO + off, lp);
        }
    };

    float2 rb[2];
    cpA(Wb, F_, sb + OFF_ST, t);
    ldB(0, rb);
    cpA(Wb + (size_t)KC * F_, F_, sb + OFF_ST + STG_SZ, t);
    cpA(Wb + (size_t)2 * KC * F_, F_, sb + OFF_ST + 2 * STG_SZ, t);

    const int NC = E_ / KC;                    // 16
    for (int c = 0; c < NC; c++) {
        const int sl = c % 3;
        cp_wait2();
        __syncthreads();                       // stage c visible; prev compute done
        stsB(rb);
        if (c + 1 < NC) ldB(c + 1, rb);
        __syncthreads();                       // B tile ready
        computeChunk(sb, sb + OFF_ST + sl * STG_SZ, acc, L, w);
        __syncthreads();                       // stage sl fully consumed
        if (c + 3 < NC) cpA(Wb + (size_t)(c + 3) * KC * F_, F_, sb + OFF_ST + sl * STG_SZ, t);
        else cp_commit();                      // empty group keeps wait arithmetic exact
    }

    // epilogue: pack hi/lo into g_H[s][b][f]
#pragma unroll
    for (int mt = 0; mt < 2; mt++) {
        const int fr = f0 + w * 32 + mt * 16 + (L >> 2);
        const float bias0 = b1[s * F_ + fr];
        const float bias1 = b1[s * F_ + fr + 8];
#pragma unroll
        for (int q = 0; q < 4; q++) {
#pragma unroll
            for (int h = 0; h < 2; h++) {
#pragma unroll
                for (int p = 0; p < 2; p++) {
                    const float v = acc[mt][q][h * 2 + p] + (h ? bias1 : bias0);
                    const float hv = __bfloat162float(__float2bfloat16_rn(v));
                    const int b = q * 8 + (L & 3) * 2 + p;
                    const int f = fr + h * 8;
                    g_H[((size_t)s * B_ + b) * F_ + f] = packbf(v, v - hv);
                }
            }
        }
    }
}

// ============================================================
// GEMM2 (k-split): D[e(256), b(32)] partial over f-half kv -> g_P[kv][b][s][e]
// grid (E/256, S, 2), 256 threads, 2 CTAs/SM
// ============================================================
__global__ __launch_bounds__(256, 2) void k_gemm2(const float* __restrict__ W2) {
    extern __shared__ char smraw[];
    const uint32_t sb = (s2u(smraw) + 1023u) & ~1023u;
    const int s = blockIdx.y, e0 = blockIdx.x * MT, kv = blockIdx.z;
    const int t = threadIdx.x, w = t >> 5, L = t & 31;

    float acc[2][4][4];
#pragma unroll
    for (int mt = 0; mt < 2; mt++)
#pragma unroll
        for (int q = 0; q < 4; q++)
#pragma unroll
            for (int r = 0; r < 4; r++) acc[mt][q][r] = 0.f;

    const float* Wb = W2 + ((size_t)s * F_ + kv * (F_ / 2)) * E_ + e0;
    const int f_base = kv * (F_ / 2);
    const int bi = t >> 4, fp0 = (t & 15) * 2;

    auto ldB = [&](int c, uint2* rb) {
#pragma unroll
        for (int i = 0; i < 2; i++)
            rb[i] = *(const uint2*)(g_H + ((size_t)s * B_ + bi + i * 16) * F_
                                    + f_base + c * KC + fp0);
    };
    auto stsB = [&](const uint2* rb) {
#pragma unroll
        for (int i = 0; i < 2; i++) {
            const uint32_t hp = (rb[i].x & 0xFFFFu) | (rb[i].y << 16);
            const uint32_t lp = (rb[i].x >> 16) | (rb[i].y & 0xFFFF0000u);
            const uint32_t off = swz((uint32_t)((bi + i * 16) * 128 + fp0 * 2));
            sts32(sb + OFF_B_HI + off, hp);
            sts32(sb + OFF_B_LO + off, lp);
        }
    };

    uint2 rb[2];
    cpA(Wb, E_, sb + OFF_ST, t);
    ldB(0, rb);
    cpA(Wb + (size_t)KC * E_, E_, sb + OFF_ST + STG_SZ, t);
    cpA(Wb + (size_t)2 * KC * E_, E_, sb + OFF_ST + 2 * STG_SZ, t);

    const int NC = (F_ / 2) / KC;              // 32
    for (int c = 0; c < NC; c++) {
        const int sl = c % 3;
        cp_wait2();
        __syncthreads();
        stsB(rb);
        if (c + 1 < NC) ldB(c + 1, rb);
        __syncthreads();
        computeChunk(sb, sb + OFF_ST + sl * STG_SZ, acc, L, w);
        __syncthreads();
        if (c + 3 < NC) cpA(Wb + (size_t)(c + 3) * KC * E_, E_, sb + OFF_ST + sl * STG_SZ, t);
        else cp_commit();
    }

    // epilogue: raw partial -> g_P[kv][b][s][e]
    float* dst = g_P[kv];
#pragma unroll
    for (int mt = 0; mt < 2; mt++) {
        const int er = e0 + w * 32 + mt * 16 + (L >> 2);
#pragma unroll
        for (int q = 0; q < 4; q++) {
#pragma unroll
            for (int h = 0; h < 2; h++) {
#pragma unroll
                for (int p = 0; p < 2; p++) {
                    const int b = q * 8 + (L & 3) * 2 + p;
                    const int e = er + h * 8;
                    dst[((size_t)b * S_ + s) * E_ + e] = acc[mt][q][h * 2 + p];
                }
            }
        }
    }
}

// ============================================================
// LN: y = p0 + p1 + b2 + x; LayerNorm over E. warp per row.
// ============================================================
__global__ void k_ln(const float* __restrict__ x, const float* __restrict__ b2,
                     const float* __restrict__ gamma, const float* __restrict__ beta,
                     float* __restrict__ out) {
    const int warp = threadIdx.x >> 5, lane = threadIdx.x & 31;
    const int row  = blockIdx.x * 8 + warp;      // row = b*S + s
    const int s    = row & (S_ - 1);
    const size_t ro = (size_t)row * E_;

    float v[16];
    float sum = 0.f, sq = 0.f;
#pragma unroll
    for (int k = 0; k < 16; k++) {
        const int e = lane + 32 * k;
        const float tv = g_P[0][ro + e] + g_P[1][ro + e] + b2[s * E_ + e] + x[ro + e];
        v[k] = tv; sum += tv; sq += tv * tv;
    }
#pragma unroll
    for (int o = 16; o; o >>= 1) {
        sum += __shfl_xor_sync(0xFFFFFFFFu, sum, o);
        sq  += __shfl_xor_sync(0xFFFFFFFFu, sq,  o);
    }
    const float mu   = sum * (1.f / E_);
    const float var  = sq * (1.f / E_) - mu * mu;
    const float rstd = rsqrtf(var + 1e-5f);

    float* orow = out + ro;
#pragma unroll
    for (int k = 0; k < 16; k++) {
        const int e = lane + 32 * k;
        orow[e] = (v[k] - mu) * rstd * gamma[e] + beta[e];
    }
}

// ============================================================
extern "C" void kernel_launch(void* const* d_in, const int* in_sizes, int n_in,
                              void* d_out, int out_size) {
    const float* x     = (const float*)d_in[0];
    const float* W1    = (const float*)d_in[1];
    const float* b1    = (const float*)d_in[2];
    const float* W2    = (const float*)d_in[3];
    const float* b2    = (const float*)d_in[4];
    const float* gamma = (const float*)d_in[5];
    const float* beta  = (const float*)d_in[6];
    float* out = (float*)d_out;

    cudaFuncSetAttribute(k_gemm1, cudaFuncAttributeMaxDynamicSharedMemorySize, SM_DYN);
    cudaFuncSetAttribute(k_gemm2, cudaFuncAttributeMaxDynamicSharedMemorySize, SM_DYN);

    k_gemm1<<<dim3(F_ / MT, S_), 256, SM_DYN>>>(x, W1, b1);
    k_gemm2<<<dim3(E_ / MT, S_, 2), 256, SM_DYN>>>(W2);
    k_ln<<<(B_ * S_) / 8, 256>>>(x, b2, gamma, beta, out);
}

// round 12
// speedup vs baseline: 1.3439x; 1.0478x over previous
#include <cuda_runtime.h>
#include <cuda_bf16.h>
#include <cstdint>

static constexpr int B_ = 32, S_ = 128, E_ = 512, F_ = 2048;
static constexpr int KC = 32;    // K per chunk
static constexpr int MT = 256;   // M tile per CTA (warp tile m32 x n32)

// SMEM: B bf16 tiles (2 bufs x 8KB) | 3-deep fp32 A stage ring
static constexpr int OFF_ST = 16384;
static constexpr int STG_SZ = 32768;             // 32 k-rows x 256 m fp32
static constexpr int SM_DYN = 16384 + 3 * STG_SZ + 128;   // 114816 -> 2 CTAs/SM

// ---- scratch ----
__device__ uint32_t g_H[(size_t)S_ * B_ * F_];      // packed (hi | lo<<16) [s][b][f]
__device__ float    g_P[2][(size_t)B_ * S_ * E_];   // gemm2 k-split partials [b][s][e]

// ============ helpers ============
__device__ __forceinline__ uint32_t s2u(const void* p) {
    uint32_t a;
    asm("{ .reg .u64 t; cvta.to.shared.u64 t, %1; cvt.u32.u64 %0, t; }" : "=r"(a) : "l"(p));
    return a;
}
__device__ __forceinline__ uint32_t packbf(float lo, float hi) {   // lo -> low 16 bits
    uint32_t r; asm("cvt.rn.bf16x2.f32 %0, %1, %2;" : "=r"(r) : "f"(hi), "f"(lo)); return r;
}
__device__ __forceinline__ float bflo(uint32_t p) { return __uint_as_float(p << 16); }
__device__ __forceinline__ float bfhi(uint32_t p) { return __uint_as_float(p & 0xFFFF0000u); }
__device__ __forceinline__ void sts32(uint32_t a, uint32_t v) {
    asm volatile("st.shared.b32 [%0], %1;" :: "r"(a), "r"(v) : "memory");
}
__device__ __forceinline__ float ldsf(uint32_t a) {
    float v; asm volatile("ld.shared.f32 %0, [%1];" : "=f"(v) : "r"(a)); return v;
}
__device__ __forceinline__ void cpasync16(uint32_t saddr, const void* g) {
    asm volatile("cp.async.cg.shared.global [%0], [%1], 16;" :: "r"(saddr), "l"(g) : "memory");
}
__device__ __forceinline__ void cp_commit() {
    asm volatile("cp.async.commit_group;" ::: "memory");
}
__device__ __forceinline__ void cp_wait1() {
    asm volatile("cp.async.wait_group 1;" ::: "memory");
}
__device__ __forceinline__ void ldmB(uint32_t* r, uint32_t addr) {  // x4: [n][k]
    asm volatile("ldmatrix.sync.aligned.m8n8.x4.shared.b16 {%0,%1,%2,%3}, [%4];"
                 : "=r"(r[0]), "=r"(r[1]), "=r"(r[2]), "=r"(r[3]) : "r"(addr));
}
__device__ __forceinline__ void mma16816(float* c, const uint32_t* a, const uint32_t* b) {
    asm volatile(
        "mma.sync.aligned.m16n8k16.row.col.f32.bf16.bf16.f32 "
        "{%0,%1,%2,%3}, {%4,%5,%6,%7}, {%8,%9}, {%0,%1,%2,%3};"
        : "+f"(c[0]), "+f"(c[1]), "+f"(c[2]), "+f"(c[3])
        : "r"(a[0]), "r"(a[1]), "r"(a[2]), "r"(a[3]), "r"(b[0]), "r"(b[1]));
}
__device__ __forceinline__ uint32_t swz(uint32_t off) { return off ^ ((off >> 3) & 0x70); }

// fp32 A stage addressing: [k][m], 1KB rows, XOR swizzle
__device__ __forceinline__ uint32_t a_addr(int k, int m) {
    return (uint32_t)(k * 1024) + (((uint32_t)(m * 4)) ^ ((uint32_t)(k & 7) << 4));
}

// ---- cp.async: raw fp32 A chunk (32 k-rows x 256 m) -> swizzled stage ----
__device__ __forceinline__ void cpA(const float* __restrict__ base, int ldw,
                                    uint32_t st, int t) {
#pragma unroll
    for (int j = 0; j < 8; j++) {
        const int id = j * 256 + t;          // 16B units
        const int kl = id >> 6, ir = id & 63;
        const uint32_t sa = st + (uint32_t)(kl * 1024)
                          + (((uint32_t)(ir * 16)) ^ ((uint32_t)(kl & 7) << 4));
        cpasync16(sa, base + (size_t)kl * ldw + ir * 4);
    }
    cp_commit();
}

// ---- build one m16k16 A fragment (hi/lo) straight from fp32 stage ----
__device__ __forceinline__ void loadAfrag(uint32_t st, int m_r, int k_c,
                                          uint32_t* ah, uint32_t* al) {
    float v0 = ldsf(st + a_addr(k_c,     m_r));
    float v1 = ldsf(st + a_addr(k_c + 1, m_r));
    float v2 = ldsf(st + a_addr(k_c,     m_r + 8));
    float v3 = ldsf(st + a_addr(k_c + 1, m_r + 8));
    float v4 = ldsf(st + a_addr(k_c + 8, m_r));
    float v5 = ldsf(st + a_addr(k_c + 9, m_r));
    float v6 = ldsf(st + a_addr(k_c + 8, m_r + 8));
    float v7 = ldsf(st + a_addr(k_c + 9, m_r + 8));
    ah[0] = packbf(v0, v1); ah[1] = packbf(v2, v3);
    ah[2] = packbf(v4, v5); ah[3] = packbf(v6, v7);
    al[0] = packbf(v0 - bflo(ah[0]), v1 - bfhi(ah[0]));
    al[1] = packbf(v2 - bflo(ah[1]), v3 - bfhi(ah[1]));
    al[2] = packbf(v4 - bflo(ah[2]), v5 - bfhi(ah[2]));
    al[3] = packbf(v6 - bflo(ah[3]), v7 - bfhi(ah[3]));
}

// ---- one KC=32 chunk: warp tile m32 x n32, A from fp32 stage, B from bf16 buf ----
__device__ __forceinline__ void computeChunk(uint32_t bufB, uint32_t st,
                                             float acc[2][4][4], int L, int w) {
    const uint32_t bHi = bufB, bLo = bufB + 4096;
#pragma unroll
    for (int ks = 0; ks < 2; ks++) {
        uint32_t bh[8], bl[8];
#pragma unroll
        for (int P = 0; P < 2; P++) {
            const uint32_t n   = (uint32_t)(P * 16 + ((L >> 4) & 1) * 8 + (L & 7));
            const uint32_t off = n * 128 +
                (((uint32_t)(ks * 32 + ((L >> 3) & 1) * 16)) ^ ((uint32_t)(L & 7) << 4));
            ldmB(bh + P * 4, bHi + off);
            ldmB(bl + P * 4, bLo + off);
        }
#pragma unroll
        for (int mt = 0; mt < 2; mt++) {
            uint32_t ah[4], al[4];
            loadAfrag(st, w * 32 + mt * 16 + (L >> 2), ks * 16 + (L & 3) * 2, ah, al);
#pragma unroll
            for (int q = 0; q < 4; q++) {
                const uint32_t* Bh = bh + (q >> 1) * 4 + (q & 1) * 2;
                const uint32_t* Bl = bl + (q >> 1) * 4 + (q & 1) * 2;
                mma16816(acc[mt][q], ah, Bh);
                mma16816(acc[mt][q], ah, Bl);
                mma16816(acc[mt][q], al, Bh);
            }
        }
    }
}

// ============================================================
// GEMM1: D[f(256), b(32)] = sum_e W1[s][e][f0+m] * x[b][s][e] ; +b1 -> g_H packed
// grid (F/256, S), 256 threads, 2 CTAs/SM
// ============================================================
__global__ __launch_bounds__(256, 2) void k_gemm1(const float* __restrict__ x,
                                                  const float* __restrict__ W1,
                                                  const float* __restrict__ b1) {
    extern __shared__ char smraw[];
    const uint32_t sb = (s2u(smraw) + 127u) & ~127u;
    const int s = blockIdx.y, f0 = blockIdx.x * MT;
    const int t = threadIdx.x, w = t >> 5, L = t & 31;

    float acc[2][4][4];
#pragma unroll
    for (int mt = 0; mt < 2; mt++)
#pragma unroll
        for (int q = 0; q < 4; q++)
#pragma unroll
            for (int r = 0; r < 4; r++) acc[mt][q][r] = 0.f;

    const float* Wb = W1 + (size_t)s * E_ * F_ + f0;
    const int bi = t >> 4, ep0 = (t & 15) * 2;

    auto ldB = [&](int c, float2* rb) {
#pragma unroll
        for (int i = 0; i < 2; i++)
            rb[i] = *(const float2*)(x + ((size_t)(bi + i * 16) * S_ + s) * E_ + c * KC + ep0);
    };
    auto stsB = [&](int sel, const float2* rb) {
        const uint32_t base = sb + (uint32_t)sel * 8192;
#pragma unroll
        for (int i = 0; i < 2; i++) {
            const uint32_t hp = packbf(rb[i].x, rb[i].y);
            const uint32_t lp = packbf(rb[i].x - bflo(hp), rb[i].y - bfhi(hp));
            const uint32_t off = swz((uint32_t)((bi + i * 16) * 128 + ep0 * 2));
            sts32(base + off, hp);
            sts32(base + 4096 + off, lp);
        }
    };

    float2 rb[2];
    cpA(Wb, F_, sb + OFF_ST, t);                       // group 0 -> slot 0
    cpA(Wb + (size_t)KC * F_, F_, sb + OFF_ST + STG_SZ, t);  // group 1 -> slot 1
    ldB(0, rb);
    stsB(0, rb);                                        // B(0) -> buf0 (pre-loop, no race)
    ldB(1, rb);                                         // rb holds B(1)

    const int NC = E_ / KC;                             // 16
    for (int c = 0; c < NC; c++) {
        cp_wait1();                                     // group c complete
        __syncthreads();                                // stage c + B(c) visible; compute c-1 done
        if (c + 2 < NC)
            cpA(Wb + (size_t)(c + 2) * KC * F_, F_, sb + OFF_ST + ((c + 2) % 3) * STG_SZ, t);
        else
            cp_commit();                                // keep wait arithmetic exact
        if (c + 1 < NC) {
            stsB((c + 1) & 1, rb);                      // B(c+1) -> other buf (not read this iter)
            if (c + 2 < NC) ldB(c + 2, rb);
        }
        computeChunk(sb + (uint32_t)(c & 1) * 8192,
                     sb + OFF_ST + (c % 3) * STG_SZ, acc, L, w);
    }

    // epilogue: pack hi/lo into g_H[s][b][f]
#pragma unroll
    for (int mt = 0; mt < 2; mt++) {
        const int fr = f0 + w * 32 + mt * 16 + (L >> 2);
        const float bias0 = b1[s * F_ + fr];
        const float bias1 = b1[s * F_ + fr + 8];
#pragma unroll
        for (int q = 0; q < 4; q++) {
#pragma unroll
            for (int h = 0; h < 2; h++) {
#pragma unroll
                for (int p = 0; p < 2; p++) {
                    const float v = acc[mt][q][h * 2 + p] + (h ? bias1 : bias0);
                    const float hv = __bfloat162float(__float2bfloat16_rn(v));
                    const int b = q * 8 + (L & 3) * 2 + p;
                    const int f = fr + h * 8;
                    g_H[((size_t)s * B_ + b) * F_ + f] = packbf(v, v - hv);
                }
            }
        }
    }
}

// ============================================================
// GEMM2 (k-split): D[e(256), b(32)] partial over f-half kv -> g_P[kv][b][s][e]
// grid (E/256, S, 2), 256 threads, 2 CTAs/SM
// ============================================================
__global__ __launch_bounds__(256, 2) void k_gemm2(const float* __restrict__ W2) {
    extern __shared__ char smraw[];
    const uint32_t sb = (s2u(smraw) + 127u) & ~127u;
    const int s = blockIdx.y, e0 = blockIdx.x * MT, kv = blockIdx.z;
    const int t = threadIdx.x, w = t >> 5, L = t & 31;

    float acc[2][4][4];
#pragma unroll
    for (int mt = 0; mt < 2; mt++)
#pragma unroll
        for (int q = 0; q < 4; q++)
#pragma unroll
            for (int r = 0; r < 4; r++) acc[mt][q][r] = 0.f;

    const float* Wb = W2 + ((size_t)s * F_ + kv * (F_ / 2)) * E_ + e0;
    const int f_base = kv * (F_ / 2);
    const int bi = t >> 4, fp0 = (t & 15) * 2;

    auto ldB = [&](int c, uint2* rb) {
#pragma unroll
        for (int i = 0; i < 2; i++)
            rb[i] = *(const uint2*)(g_H + ((size_t)s * B_ + bi + i * 16) * F_
                                    + f_base + c * KC + fp0);
    };
    auto stsB = [&](int sel, const uint2* rb) {
        const uint32_t base = sb + (uint32_t)sel * 8192;
#pragma unroll
        for (int i = 0; i < 2; i++) {
            const uint32_t hp = (rb[i].x & 0xFFFFu) | (rb[i].y << 16);
            const uint32_t lp = (rb[i].x >> 16) | (rb[i].y & 0xFFFF0000u);
            const uint32_t off = swz((uint32_t)((bi + i * 16) * 128 + fp0 * 2));
            sts32(base + off, hp);
            sts32(base + 4096 + off, lp);
        }
    };

    uint2 rb[2];
    cpA(Wb, E_, sb + OFF_ST, t);
    cpA(Wb + (size_t)KC * E_, E_, sb + OFF_ST + STG_SZ, t);
    ldB(0, rb);
    stsB(0, rb);
    ldB(1, rb);

    const int NC = (F_ / 2) / KC;                       // 32
    for (int c = 0; c < NC; c++) {
        cp_wait1();
        __syncthreads();
        if (c + 2 < NC)
            cpA(Wb + (size_t)(c + 2) * KC * E_, E_, sb + OFF_ST + ((c + 2) % 3) * STG_SZ, t);
        else
            cp_commit();
        if (c + 1 < NC) {
            stsB((c + 1) & 1, rb);
            if (c + 2 < NC) ldB(c + 2, rb);
        }
        computeChunk(sb + (uint32_t)(c & 1) * 8192,
                     sb + OFF_ST + (c % 3) * STG_SZ, acc, L, w);
    }

    // epilogue: raw partial -> g_P[kv][b][s][e]
    float* dst = g_P[kv];
#pragma unroll
    for (int mt = 0; mt < 2; mt++) {
        const int er = e0 + w * 32 + mt * 16 + (L >> 2);
#pragma unroll
        for (int q = 0; q < 4; q++) {
#pragma unroll
            for (int h = 0; h < 2; h++) {
#pragma unroll
                for (int p = 0; p < 2; p++) {
                    const int b = q * 8 + (L & 3) * 2 + p;
                    const int e = er + h * 8;
                    dst[((size_t)b * S_ + s) * E_ + e] = acc[mt][q][h * 2 + p];
                }
            }
        }
    }
}

// ============================================================
// LN: y = p0 + p1 + b2 + x; LayerNorm over E. warp per row.
// ============================================================
__global__ void k_ln(const float* __restrict__ x, const float* __restrict__ b2,
                     const float* __restrict__ gamma, const float* __restrict__ beta,
                     float* __restrict__ out) {
    const int warp = threadIdx.x >> 5, lane = threadIdx.x & 31;
    const int row  = blockIdx.x * 8 + warp;      // row = b*S + s
    const int s    = row & (S_ - 1);
    const size_t ro = (size_t)row * E_;

    float v[16];
    float sum = 0.f, sq = 0.f;
#pragma unroll
    for (int k = 0; k < 16; k++) {
        const int e = lane + 32 * k;
        const float tv = g_P[0][ro + e] + g_P[1][ro + e] + b2[s * E_ + e] + x[ro + e];
        v[k] = tv; sum += tv; sq += tv * tv;
    }
#pragma unroll
    for (int o = 16; o; o >>= 1) {
        sum += __shfl_xor_sync(0xFFFFFFFFu, sum, o);
        sq  += __shfl_xor_sync(0xFFFFFFFFu, sq,  o);
    }
    const float mu   = sum * (1.f / E_);
    const float var  = sq * (1.f / E_) - mu * mu;
    const float rstd = rsqrtf(var + 1e-5f);

    float* orow = out + ro;
#pragma unroll
    for (int k = 0; k < 16; k++) {
        const int e = lane + 32 * k;
        orow[e] = (v[k] - mu) * rstd * gamma[e] + beta[e];
    }
}

// ============================================================
extern "C" void kernel_launch(void* const* d_in, const int* in_sizes, int n_in,
                              void* d_out, int out_size) {
    const float* x     = (const float*)d_in[0];
    const float* W1    = (const float*)d_in[1];
    const float* b1    = (const float*)d_in[2];
    const float* W2    = (const float*)d_in[3];
    const float* b2    = (const float*)d_in[4];
    const float* gamma = (const float*)d_in[5];
    const float* beta  = (const float*)d_in[6];
    float* out = (float*)d_out;

    cudaFuncSetAttribute(k_gemm1, cudaFuncAttributeMaxDynamicSharedMemorySize, SM_DYN);
    cudaFuncSetAttribute(k_gemm2, cudaFuncAttributeMaxDynamicSharedMemorySize, SM_DYN);

    k_gemm1<<<dim3(F_ / MT, S_), 256, SM_DYN>>>(x, W1, b1);
    k_gemm2<<<dim3(E_ / MT, S_, 2), 256, SM_DYN>>>(W2);
    k_ln<<<(B_ * S_) / 8, 256>>>(x, b2, gamma, beta, out);
}